// round 14
// baseline (speedup 1.0000x reference)
#include <cuda_runtime.h>
#include <cuda_bf16.h>
#include <cstdint>

#define BB   2
#define SS   2048
#define HH   16
#define DK   64
#define DM   1024
#define MM   (BB*SS)
#define OUT_ELEMS  (4194304)

// Scratch (allocation-free rule: device globals)
__device__ __nv_bfloat16 g_xqh[MM*DM], g_xql[MM*DM];   // query  hi/lo [M,K]
__device__ __nv_bfloat16 g_xkh[MM*DM], g_xkl[MM*DM];   // key    hi/lo
__device__ __nv_bfloat16 g_xvh[MM*DM], g_xvl[MM*DM];   // value  hi/lo
__device__ __nv_bfloat16 g_wqh[DM*DM], g_wql[DM*DM];   // Wq hi/lo [N,K]
__device__ __nv_bfloat16 g_wkh[DM*DM], g_wkl[DM*DM];
__device__ __nv_bfloat16 g_wvh[DM*DM], g_wvl[DM*DM];
__device__ __nv_bfloat16 g_wfh[DM*DM], g_wfl[DM*DM];
__device__ __nv_bfloat16 g_qh[BB*HH*SS*DK], g_ql[BB*HH*SS*DK];  // q proj hi/lo [bh][s][d]
__device__ __nv_bfloat16 g_kh[BB*HH*SS*DK], g_kl[BB*HH*SS*DK];  // k proj hi/lo
__device__ float g_v[BB*HH*DK*SS];                               // v fp32 [bh][d][s]
__device__ __nv_bfloat16 g_aoh[MM*DM], g_aol[MM*DM];             // attn_out hi/lo (b,s,h,d)

// single dynamic-smem symbol (used by gemm_lg)
extern __shared__ char dynsm[];

// ---------------------------------------------------------------------------
__device__ __forceinline__ void mma16(float* c, const uint32_t* a, const uint32_t* b) {
    asm volatile("mma.sync.aligned.m16n8k16.row.col.f32.bf16.bf16.f32 "
        "{%0,%1,%2,%3},{%4,%5,%6,%7},{%8,%9},{%0,%1,%2,%3};"
        : "+f"(c[0]), "+f"(c[1]), "+f"(c[2]), "+f"(c[3])
        : "r"(a[0]), "r"(a[1]), "r"(a[2]), "r"(a[3]), "r"(b[0]), "r"(b[1]));
}

__device__ __forceinline__ void ldsm4(uint32_t* r, uint32_t addr) {
    asm volatile("ldmatrix.sync.aligned.m8n8.x4.shared.b16 {%0,%1,%2,%3}, [%4];"
        : "=r"(r[0]), "=r"(r[1]), "=r"(r[2]), "=r"(r[3]) : "r"(addr));
}

__device__ __forceinline__ uint32_t smem_u32(const void* p) {
    return (uint32_t)__cvta_generic_to_shared(p);
}

__device__ __forceinline__ void cp16(uint32_t dst, const void* src) {
    asm volatile("cp.async.cg.shared.global [%0], [%1], 16;" :: "r"(dst), "l"(src));
}

// convert 4 floats -> 4 hi bf16 (8B) + 4 lo bf16 (8B)
__device__ __forceinline__ void cvt_hilo(const float4 v, uint2* ph, uint2* pl) {
    __nv_bfloat162 h0 = __floats2bfloat162_rn(v.x, v.y);
    __nv_bfloat162 h1 = __floats2bfloat162_rn(v.z, v.w);
    __nv_bfloat162 l0 = __floats2bfloat162_rn(v.x - __bfloat162float(h0.x),
                                              v.y - __bfloat162float(h0.y));
    __nv_bfloat162 l1 = __floats2bfloat162_rn(v.z - __bfloat162float(h1.x),
                                              v.w - __bfloat162float(h1.y));
    *ph = make_uint2(*(uint32_t*)&h0, *(uint32_t*)&h1);
    *pl = make_uint2(*(uint32_t*)&l0, *(uint32_t*)&l1);
}

// ===========================================================================
// Elementwise pre-pass: fp32 -> bf16 hi/lo pair arrays
// ===========================================================================
__global__ void __launch_bounds__(256) cvt_pass(
    const float4* __restrict__ in, uint2* __restrict__ oh, uint2* __restrict__ ol, int n4)
{
    int i = blockIdx.x * 256 + threadIdx.x;
    if (i < n4) {
        uint2 h, l;
        cvt_hilo(in[i], &h, &l);
        oh[i] = h;
        ol[i] = l;
    }
}

// ===========================================================================
// gemm_b16: pure-bf16-input NT GEMM (bf16x3 split). 128x128 tile, BK=32.
// 8 warps (4Mx2N), warp tile 32x64. C = scale*(A@B^T)(+bias).
// A: [M,K] hi/lo bf16, B: [N,K] hi/lo bf16.
// MODE: 0 fp32 row-major C; 1 bf16 hi/lo scatter [b,h,s,d]; 2 fp32 scatter [b,h,d,s]
// ===========================================================================
template<int MODE>
__global__ void __launch_bounds__(256, 2) gemm_b16(
    const __nv_bfloat16* __restrict__ Agh, const __nv_bfloat16* __restrict__ Agl,
    const __nv_bfloat16* __restrict__ Bgh, const __nv_bfloat16* __restrict__ Bgl,
    const float* __restrict__ bias, float* __restrict__ C,
    __nv_bfloat16* __restrict__ Ch, __nv_bfloat16* __restrict__ Cl,
    int N, int K, float scale)
{
    constexpr int BK = 32, SK = 40;  // 80B rows: 5r mod 8 -> conflict-free ldsm

    __shared__ __nv_bfloat16 Ah[128 * SK], Al[128 * SK];
    __shared__ __nv_bfloat16 Bh[128 * SK], Bl[128 * SK];   // 40960 B total

    const int tid = threadIdx.x, w = tid >> 5, lane = tid & 31;
    const int g = lane >> 2, t = lane & 3;
    const int m0 = blockIdx.y * 128, n0 = blockIdx.x * 128;
    const int wm0 = (w & 3) * 32, wn0 = (w >> 2) * 64;

    const uint32_t ah_b = smem_u32(Ah), al_b = smem_u32(Al);
    const uint32_t bh_b = smem_u32(Bh), bl_b = smem_u32(Bl);

    float acc[2][8][4];
    #pragma unroll
    for (int i = 0; i < 2; i++)
        #pragma unroll
        for (int j = 0; j < 8; j++)
            #pragma unroll
            for (int e = 0; e < 4; e++) acc[i][j][e] = 0.f;

    for (int k0 = 0; k0 < K; k0 += BK) {
        __syncthreads();   // previous chunk's readers done before overwrite
        // stage: 4 arrays x 512 16B-chunks, 2 per thread per array
        #pragma unroll
        for (int i = 0; i < 2; i++) {
            int idx = tid + i * 256;
            int r = idx >> 2, c = idx & 3;
            uint32_t so = (uint32_t)(r * SK + c * 8) * 2;
            long long ao = (long long)(m0 + r) * K + k0 + c * 8;
            long long bo = (long long)(n0 + r) * K + k0 + c * 8;
            cp16(ah_b + so, Agh + ao);
            cp16(al_b + so, Agl + ao);
            cp16(bh_b + so, Bgh + bo);
            cp16(bl_b + so, Bgl + bo);
        }
        asm volatile("cp.async.commit_group;");
        asm volatile("cp.async.wait_group 0;");
        __syncthreads();

        #pragma unroll
        for (int ks = 0; ks < 2; ks++) {
            const int arow = wm0 + (lane & 7) + ((lane >> 3) & 1) * 8;
            const int acol = ks * 16 + (lane >> 4) * 8;
            const int brow = wn0 + (lane & 7) + (lane >> 4) * 8;
            const int bcol = ((lane >> 3) & 1) * 8 + ks * 16;

            uint32_t af[2][4], afl[2][4], bf[4][4], bfl[4][4];
            #pragma unroll
            for (int f = 0; f < 2; f++) {
                uint32_t off = ((arow + f * 16) * SK + acol) * 2;
                ldsm4(af[f],  ah_b + off);
                ldsm4(afl[f], al_b + off);
            }
            #pragma unroll
            for (int p = 0; p < 4; p++) {
                uint32_t off = ((brow + p * 16) * SK + bcol) * 2;
                ldsm4(bf[p],  bh_b + off);
                ldsm4(bfl[p], bl_b + off);
            }

            #pragma unroll
            for (int mf = 0; mf < 2; mf++)
                #pragma unroll
                for (int nf = 0; nf < 8; nf++) {
                    const uint32_t* bp = &bf[nf >> 1][(nf & 1) * 2];
                    const uint32_t* lp = &bfl[nf >> 1][(nf & 1) * 2];
                    mma16(acc[mf][nf], afl[mf], bp);
                    mma16(acc[mf][nf], af[mf],  lp);
                    mma16(acc[mf][nf], af[mf],  bp);
                }
        }
    }

    #pragma unroll
    for (int mf = 0; mf < 2; mf++) {
        #pragma unroll
        for (int nf = 0; nf < 8; nf++) {
            const int gn = n0 + wn0 + nf * 8 + 2 * t;
            float b0 = 0.f, b1 = 0.f;
            if (bias) { b0 = __ldg(&bias[gn]); b1 = __ldg(&bias[gn + 1]); }
            #pragma unroll
            for (int h = 0; h < 2; h++) {
                const int gm = m0 + wm0 + mf * 16 + g + h * 8;
                float v0 = acc[mf][nf][h * 2 + 0] * scale + b0;
                float v1 = acc[mf][nf][h * 2 + 1] * scale + b1;
                if (MODE == 0) {
                    float2 p = {v0, v1};
                    *(float2*)&C[(long long)gm * N + gn] = p;
                } else if (MODE == 1) {
                    int b = gm >> 11, s = gm & (SS - 1);
                    int hh = gn >> 6, d = gn & 63;
                    long long idx = (((long long)(b * HH + hh)) * SS + s) * DK + d;
                    __nv_bfloat162 hp = __floats2bfloat162_rn(v0, v1);
                    __nv_bfloat162 lp = __floats2bfloat162_rn(v0 - __bfloat162float(hp.x),
                                                              v1 - __bfloat162float(hp.y));
                    *(uint32_t*)&Ch[idx] = *(uint32_t*)&hp;
                    *(uint32_t*)&Cl[idx] = *(uint32_t*)&lp;
                } else { // MODE 2
                    int b = gm >> 11, s = gm & (SS - 1);
                    int hh = gn >> 6, d = gn & 63;
                    C[(((long long)(b * HH + hh)) * DK + d) * SS + s] = v0;
                    C[(((long long)(b * HH + hh)) * DK + d + 1) * SS + s] = v1;
                }
            }
        }
    }
}

// ===========================================================================
// gemm_pv (R7 PV core): P @ V^T per head, 128x64 tile, BK=32.
// Output: bf16 hi/lo attn_out, (b,s,h,d) flat.
// ===========================================================================
__global__ void __launch_bounds__(256, 2) gemm_pv(
    const float* __restrict__ attn, const float* __restrict__ V,
    __nv_bfloat16* __restrict__ aoh, __nv_bfloat16* __restrict__ aol)
{
    constexpr int BK = 32, SK = 40;

    __shared__ __nv_bfloat16 Ah[128 * SK], Al[128 * SK];
    __shared__ __nv_bfloat16 Bh[64 * SK],  Bl[64 * SK];

    const int bz = blockIdx.z;
    const float* A = attn + (long long)bz * SS * SS;
    const float* B = V + (long long)bz * DK * SS;
    const int K = SS;

    const int tid = threadIdx.x, w = tid >> 5, lane = tid & 31;
    const int g = lane >> 2, t = lane & 3;
    const int m0 = blockIdx.y * 128;
    const int wm0 = (w & 3) * 32, wn0 = (w >> 2) * 32;

    const uint32_t ah_b = smem_u32(Ah), al_b = smem_u32(Al);
    const uint32_t bh_b = smem_u32(Bh), bl_b = smem_u32(Bl);

    float acc[2][4][4];
    #pragma unroll
    for (int i = 0; i < 2; i++)
        #pragma unroll
        for (int j = 0; j < 4; j++)
            #pragma unroll
            for (int e = 0; e < 4; e++) acc[i][j][e] = 0.f;

    float4 ra[4], rb[2];
    #pragma unroll
    for (int i = 0; i < 4; i++) {
        int idx = tid + i * 256;
        ra[i] = *(const float4*)(A + (long long)(m0 + (idx >> 3)) * K + (idx & 7) * 4);
    }
    #pragma unroll
    for (int i = 0; i < 2; i++) {
        int idx = tid + i * 256;
        rb[i] = *(const float4*)(B + (long long)(idx >> 3) * K + (idx & 7) * 4);
    }

    for (int k0 = 0; k0 < K; k0 += BK) {
        __syncthreads();
        #pragma unroll
        for (int i = 0; i < 4; i++) {
            int idx = tid + i * 256, r = idx >> 3, c = (idx & 7) * 4;
            cvt_hilo(ra[i], (uint2*)&Ah[r * SK + c], (uint2*)&Al[r * SK + c]);
        }
        #pragma unroll
        for (int i = 0; i < 2; i++) {
            int idx = tid + i * 256, r = idx >> 3, c = (idx & 7) * 4;
            cvt_hilo(rb[i], (uint2*)&Bh[r * SK + c], (uint2*)&Bl[r * SK + c]);
        }
        __syncthreads();

        if (k0 + BK < K) {
            #pragma unroll
            for (int i = 0; i < 4; i++) {
                int idx = tid + i * 256;
                ra[i] = *(const float4*)(A + (long long)(m0 + (idx >> 3)) * K + k0 + BK + (idx & 7) * 4);
            }
            #pragma unroll
            for (int i = 0; i < 2; i++) {
                int idx = tid + i * 256;
                rb[i] = *(const float4*)(B + (long long)(idx >> 3) * K + k0 + BK + (idx & 7) * 4);
            }
        }

        #pragma unroll
        for (int ks = 0; ks < 2; ks++) {
            const int arow = wm0 + (lane & 7) + ((lane >> 3) & 1) * 8;
            const int acol = ks * 16 + (lane >> 4) * 8;
            const int brow = wn0 + (lane & 7) + (lane >> 4) * 8;
            const int bcol = ((lane >> 3) & 1) * 8 + ks * 16;

            uint32_t af[2][4], afl[2][4], bf[2][4], bfl[2][4];
            #pragma unroll
            for (int f = 0; f < 2; f++) {
                uint32_t off = ((arow + f * 16) * SK + acol) * 2;
                ldsm4(af[f],  ah_b + off);
                ldsm4(afl[f], al_b + off);
            }
            #pragma unroll
            for (int p = 0; p < 2; p++) {
                uint32_t off = ((brow + p * 16) * SK + bcol) * 2;
                ldsm4(bf[p],  bh_b + off);
                ldsm4(bfl[p], bl_b + off);
            }

            #pragma unroll
            for (int mf = 0; mf < 2; mf++)
                #pragma unroll
                for (int nf = 0; nf < 4; nf++) {
                    const uint32_t* bp = &bf[nf >> 1][(nf & 1) * 2];
                    const uint32_t* lp = &bfl[nf >> 1][(nf & 1) * 2];
                    mma16(acc[mf][nf], afl[mf], bp);
                    mma16(acc[mf][nf], af[mf],  lp);
                    mma16(acc[mf][nf], af[mf],  bp);
                }
        }
    }

    const int b = bz >> 4, head = bz & 15;
    #pragma unroll
    for (int mf = 0; mf < 2; mf++) {
        #pragma unroll
        for (int nf = 0; nf < 4; nf++) {
            const int gn = wn0 + nf * 8 + 2 * t;
            #pragma unroll
            for (int h = 0; h < 2; h++) {
                const int gm = m0 + wm0 + mf * 16 + g + h * 8;
                float v0 = acc[mf][nf][h * 2], v1 = acc[mf][nf][h * 2 + 1];
                long long idx = ((long long)(b * SS + gm)) * DM + head * DK + gn;
                __nv_bfloat162 hp = __floats2bfloat162_rn(v0, v1);
                __nv_bfloat162 lp = __floats2bfloat162_rn(v0 - __bfloat162float(hp.x),
                                                          v1 - __bfloat162float(hp.y));
                *(uint32_t*)&aoh[idx] = *(uint32_t*)&hp;
                *(uint32_t*)&aol[idx] = *(uint32_t*)&lp;
            }
        }
    }
}

// ===========================================================================
// Logits GEMM (proven R7): bf16 hi/lo inputs via cp.async. C=(q@k^T)/8 per head.
// ===========================================================================
__global__ void __launch_bounds__(256, 2) gemm_lg(
    const __nv_bfloat16* __restrict__ Qh, const __nv_bfloat16* __restrict__ Ql,
    const __nv_bfloat16* __restrict__ Kh, const __nv_bfloat16* __restrict__ Kl,
    float* __restrict__ C)
{
    constexpr int SK = 72;
    __nv_bfloat16* sm = (__nv_bfloat16*)dynsm;
    __nv_bfloat16* tiles[4] = { sm, sm + 128 * SK, sm + 2 * 128 * SK, sm + 3 * 128 * SK };

    const int bh = blockIdx.z;
    const int tid = threadIdx.x, w = tid >> 5, lane = tid & 31;
    const int g = lane >> 2, t = lane & 3;
    const int m0 = blockIdx.y * 128, n0 = blockIdx.x * 128;
    const int wm0 = (w & 3) * 32, wn0 = (w >> 2) * 64;

    const __nv_bfloat16* srcs[4] = {
        Qh + (long long)bh * SS * DK + (long long)m0 * DK,
        Ql + (long long)bh * SS * DK + (long long)m0 * DK,
        Kh + (long long)bh * SS * DK + (long long)n0 * DK,
        Kl + (long long)bh * SS * DK + (long long)n0 * DK };

    #pragma unroll
    for (int a = 0; a < 4; a++) {
        uint32_t dst = smem_u32(tiles[a]);
        #pragma unroll
        for (int i = 0; i < 4; i++) {
            int idx = tid + i * 256;
            int r = idx >> 3, c = idx & 7;
            cp16(dst + (r * SK + c * 8) * 2, srcs[a] + r * 64 + c * 8);
        }
    }
    asm volatile("cp.async.commit_group;");
    asm volatile("cp.async.wait_group 0;");
    __syncthreads();

    const uint32_t ah_b = smem_u32(tiles[0]), al_b = smem_u32(tiles[1]);
    const uint32_t bh_b = smem_u32(tiles[2]), bl_b = smem_u32(tiles[3]);

    float acc[2][8][4];
    #pragma unroll
    for (int i = 0; i < 2; i++)
        #pragma unroll
        for (int j = 0; j < 8; j++)
            #pragma unroll
            for (int e = 0; e < 4; e++) acc[i][j][e] = 0.f;

    #pragma unroll
    for (int ks = 0; ks < 4; ks++) {
        const int arow = wm0 + (lane & 7) + ((lane >> 3) & 1) * 8;
        const int acol = ks * 16 + (lane >> 4) * 8;
        const int brow = wn0 + (lane & 7) + (lane >> 4) * 8;
        const int bcol = ((lane >> 3) & 1) * 8 + ks * 16;

        uint32_t af[2][4], afl[2][4], bf[4][4], bfl[4][4];
        #pragma unroll
        for (int f = 0; f < 2; f++) {
            uint32_t off = ((arow + f * 16) * SK + acol) * 2;
            ldsm4(af[f],  ah_b + off);
            ldsm4(afl[f], al_b + off);
        }
        #pragma unroll
        for (int p = 0; p < 4; p++) {
            uint32_t off = ((brow + p * 16) * SK + bcol) * 2;
            ldsm4(bf[p],  bh_b + off);
            ldsm4(bfl[p], bl_b + off);
        }

        #pragma unroll
        for (int mf = 0; mf < 2; mf++)
            #pragma unroll
            for (int nf = 0; nf < 8; nf++) {
                const uint32_t* bp = &bf[nf >> 1][(nf & 1) * 2];
                const uint32_t* lp = &bfl[nf >> 1][(nf & 1) * 2];
                mma16(acc[mf][nf], afl[mf], bp);
                mma16(acc[mf][nf], af[mf],  lp);
                mma16(acc[mf][nf], af[mf],  bp);
            }
    }

    float* Cb = C + (long long)bh * SS * SS;
    #pragma unroll
    for (int mf = 0; mf < 2; mf++)
        #pragma unroll
        for (int nf = 0; nf < 8; nf++) {
            const int gn = n0 + wn0 + nf * 8 + 2 * t;
            #pragma unroll
            for (int h = 0; h < 2; h++) {
                const int gm = m0 + wm0 + mf * 16 + g + h * 8;
                float2 p = {acc[mf][nf][h * 2] * 0.125f, acc[mf][nf][h * 2 + 1] * 0.125f};
                *(float2*)&Cb[(long long)gm * SS + gn] = p;
            }
        }
}

// ===========================================================================
// Sparsemax (proven R7): one WARP per row of 2048, in-place, shfl-only.
// ===========================================================================
__global__ void __launch_bounds__(256) sparsemax_kernel(float* __restrict__ attn)
{
    const int row = blockIdx.x * 8 + (threadIdx.x >> 5);
    const int lane = threadIdx.x & 31;
    float* z = attn + (long long)row * SS;

    float4 v[16];
    #pragma unroll
    for (int i = 0; i < 16; i++) v[i] = *(const float4*)(z + i * 128 + lane * 4);

    float mx = -1e30f;
    #pragma unroll
    for (int i = 0; i < 16; i++)
        mx = fmaxf(mx, fmaxf(fmaxf(v[i].x, v[i].y), fmaxf(v[i].z, v[i].w)));
    #pragma unroll
    for (int o = 16; o; o >>= 1) mx = fmaxf(mx, __shfl_xor_sync(0xffffffffu, mx, o));

    float lo = mx - 1.f, hi = mx;
    for (int it = 0; it < 12; it++) {
        float mid = 0.5f * (lo + hi);
        float s = 0.f;
        #pragma unroll
        for (int i = 0; i < 16; i++) {
            s += fmaxf(v[i].x - mid, 0.f) + fmaxf(v[i].y - mid, 0.f);
            s += fmaxf(v[i].z - mid, 0.f) + fmaxf(v[i].w - mid, 0.f);
        }
        #pragma unroll
        for (int o = 16; o; o >>= 1) s += __shfl_xor_sync(0xffffffffu, s, o);
        if (s >= 1.f) lo = mid; else hi = mid;
    }

    float tau = lo;
    for (int it = 0; it < 8; it++) {
        float s = 0.f, c = 0.f;
        #pragma unroll
        for (int i = 0; i < 16; i++) {
            if (v[i].x > tau) { s += v[i].x; c += 1.f; }
            if (v[i].y > tau) { s += v[i].y; c += 1.f; }
            if (v[i].z > tau) { s += v[i].z; c += 1.f; }
            if (v[i].w > tau) { s += v[i].w; c += 1.f; }
        }
        #pragma unroll
        for (int o = 16; o; o >>= 1) {
            s += __shfl_xor_sync(0xffffffffu, s, o);
            c += __shfl_xor_sync(0xffffffffu, c, o);
        }
        float nt = (s - 1.f) / c;   // c >= 1 (row max in support)
        if (nt == tau) break;
        tau = nt;
    }

    #pragma unroll
    for (int i = 0; i < 16; i++) {
        float4 o;
        o.x = fmaxf(v[i].x - tau, 0.f);
        o.y = fmaxf(v[i].y - tau, 0.f);
        o.z = fmaxf(v[i].z - tau, 0.f);
        o.w = fmaxf(v[i].w - tau, 0.f);
        *(float4*)(z + i * 128 + lane * 4) = o;
    }
}

// ---------------------------------------------------------------------------
extern "C" void kernel_launch(void* const* d_in, const int* in_sizes, int n_in,
                              void* d_out, int out_size)
{
    const float* query = (const float*)d_in[0];
    const float* key   = (const float*)d_in[1];
    const float* value = (const float*)d_in[2];
    const float* Wq  = (const float*)d_in[3];  const float* bq  = (const float*)d_in[4];
    const float* Wk  = (const float*)d_in[5];  const float* bk  = (const float*)d_in[6];
    const float* Wv  = (const float*)d_in[7];  const float* bv  = (const float*)d_in[8];
    const float* Wfc = (const float*)d_in[9];  const float* bfc = (const float*)d_in[10];

    float* out  = (float*)d_out;
    float* attn = out + OUT_ELEMS;

    __nv_bfloat16 *xqh, *xql, *xkh, *xkl, *xvh, *xvl;
    __nv_bfloat16 *wqh, *wql, *wkh, *wkl, *wvh, *wvl, *wfh, *wfl;
    __nv_bfloat16 *pqh, *pql, *pkh, *pkl, *aoh, *aol;
    float *pv;
    cudaGetSymbolAddress((void**)&xqh, g_xqh); cudaGetSymbolAddress((void**)&xql, g_xql);
    cudaGetSymbolAddress((void**)&xkh, g_xkh); cudaGetSymbolAddress((void**)&xkl, g_xkl);
    cudaGetSymbolAddress((void**)&xvh, g_xvh); cudaGetSymbolAddress((void**)&xvl, g_xvl);
    cudaGetSymbolAddress((void**)&wqh, g_wqh); cudaGetSymbolAddress((void**)&wql, g_wql);
    cudaGetSymbolAddress((void**)&wkh, g_wkh); cudaGetSymbolAddress((void**)&wkl, g_wkl);
    cudaGetSymbolAddress((void**)&wvh, g_wvh); cudaGetSymbolAddress((void**)&wvl, g_wvl);
    cudaGetSymbolAddress((void**)&wfh, g_wfh); cudaGetSymbolAddress((void**)&wfl, g_wfl);
    cudaGetSymbolAddress((void**)&pqh, g_qh);  cudaGetSymbolAddress((void**)&pql, g_ql);
    cudaGetSymbolAddress((void**)&pkh, g_kh);  cudaGetSymbolAddress((void**)&pkl, g_kl);
    cudaGetSymbolAddress((void**)&aoh, g_aoh); cudaGetSymbolAddress((void**)&aol, g_aol);
    cudaGetSymbolAddress((void**)&pv,  g_v);

    const int LG_SMEM = 4 * 128 * 72 * 2;  // 73728 B
    cudaFuncSetAttribute(gemm_lg, cudaFuncAttributeMaxDynamicSharedMemorySize, LG_SMEM);

    dim3 blk(256);
    const int NA4 = MM * DM / 4;   // activation float4 count (1M)
    const int NW4 = DM * DM / 4;   // weight float4 count (256K)

    // 0) pre-convert activations + weights to bf16 hi/lo (one-time)
    cvt_pass<<<NA4 / 256, blk>>>((const float4*)query, (uint2*)xqh, (uint2*)xql, NA4);
    cvt_pass<<<NA4 / 256, blk>>>((const float4*)key,   (uint2*)xkh, (uint2*)xkl, NA4);
    cvt_pass<<<NA4 / 256, blk>>>((const float4*)value, (uint2*)xvh, (uint2*)xvl, NA4);
    cvt_pass<<<NW4 / 256, blk>>>((const float4*)Wq,  (uint2*)wqh, (uint2*)wql, NW4);
    cvt_pass<<<NW4 / 256, blk>>>((const float4*)Wk,  (uint2*)wkh, (uint2*)wkl, NW4);
    cvt_pass<<<NW4 / 256, blk>>>((const float4*)Wv,  (uint2*)wvh, (uint2*)wvl, NW4);
    cvt_pass<<<NW4 / 256, blk>>>((const float4*)Wfc, (uint2*)wfh, (uint2*)wfl, NW4);

    // 1) Projections (pure-bf16 GEMM): q,k -> bf16 hi/lo head-major; v -> fp32 [bh][d][s]
    gemm_b16<1><<<dim3(DM/128, MM/128, 1), blk>>>(xqh, xql, wqh, wql, bq, nullptr, pqh, pql, DM, DM, 1.f);
    gemm_b16<1><<<dim3(DM/128, MM/128, 1), blk>>>(xkh, xkl, wkh, wkl, bk, nullptr, pkh, pkl, DM, DM, 1.f);
    gemm_b16<2><<<dim3(DM/128, MM/128, 1), blk>>>(xvh, xvl, wvh, wvl, bv, pv, nullptr, nullptr, DM, DM, 1.f);

    // 2) logits = q @ k^T / 8 -> attention slice of d_out
    gemm_lg<<<dim3(SS/128, SS/128, BB*HH), blk, LG_SMEM>>>(pqh, pql, pkh, pkl, attn);

    // 3) sparsemax in place (warp per row)
    sparsemax_kernel<<<BB*HH*SS/8, 256>>>(attn);

    // 4) attn_out = P @ V^T -> bf16 hi/lo (b,s,h,d) flat
    gemm_pv<<<dim3(1, SS/128, BB*HH), blk>>>(attn, pv, aoh, aol);

    // 5) output = attn_out @ Wfc^T + bfc (pure-bf16 GEMM)
    gemm_b16<0><<<dim3(DM/128, MM/128, 1), blk>>>(aoh, aol, wfh, wfl, bfc, out, nullptr, nullptr, DM, DM, 1.f);
}

// round 16
// speedup vs baseline: 1.0255x; 1.0255x over previous
#include <cuda_runtime.h>
#include <cuda_bf16.h>
#include <cstdint>

#define BB   2
#define SS   2048
#define HH   16
#define DK   64
#define DM   1024
#define MM   (BB*SS)
#define OUT_ELEMS  (4194304)

// Scratch (allocation-free rule: device globals)
__device__ __nv_bfloat16 g_qh[BB*HH*SS*DK], g_ql[BB*HH*SS*DK];  // q proj hi/lo [bh][s][d]
__device__ __nv_bfloat16 g_kh[BB*HH*SS*DK], g_kl[BB*HH*SS*DK];  // k proj hi/lo
__device__ __nv_bfloat16 g_vh[BB*HH*SS*DK], g_vl[BB*HH*SS*DK];  // v proj hi/lo [bh][s][d]
__device__ float g_ao[MM*DM];                                    // attn_out fp32 (b,s,h,d)

// single dynamic-smem symbol (used by gemm_lg)
extern __shared__ char dynsm[];

// ---------------------------------------------------------------------------
__device__ __forceinline__ void mma16(float* c, const uint32_t* a, const uint32_t* b) {
    asm volatile("mma.sync.aligned.m16n8k16.row.col.f32.bf16.bf16.f32 "
        "{%0,%1,%2,%3},{%4,%5,%6,%7},{%8,%9},{%0,%1,%2,%3};"
        : "+f"(c[0]), "+f"(c[1]), "+f"(c[2]), "+f"(c[3])
        : "r"(a[0]), "r"(a[1]), "r"(a[2]), "r"(a[3]), "r"(b[0]), "r"(b[1]));
}

__device__ __forceinline__ void ldsm4(uint32_t* r, uint32_t addr) {
    asm volatile("ldmatrix.sync.aligned.m8n8.x4.shared.b16 {%0,%1,%2,%3}, [%4];"
        : "=r"(r[0]), "=r"(r[1]), "=r"(r[2]), "=r"(r[3]) : "r"(addr));
}

__device__ __forceinline__ void ldsm4t(uint32_t* r, uint32_t addr) {
    asm volatile("ldmatrix.sync.aligned.m8n8.x4.trans.shared.b16 {%0,%1,%2,%3}, [%4];"
        : "=r"(r[0]), "=r"(r[1]), "=r"(r[2]), "=r"(r[3]) : "r"(addr));
}

__device__ __forceinline__ uint32_t smem_u32(const void* p) {
    return (uint32_t)__cvta_generic_to_shared(p);
}

__device__ __forceinline__ void cp16(uint32_t dst, const void* src) {
    asm volatile("cp.async.cg.shared.global [%0], [%1], 16;" :: "r"(dst), "l"(src));
}

// convert 4 floats -> 4 hi bf16 (8B) + 4 lo bf16 (8B)
__device__ __forceinline__ void cvt_hilo(const float4 v, uint2* ph, uint2* pl) {
    __nv_bfloat162 h0 = __floats2bfloat162_rn(v.x, v.y);
    __nv_bfloat162 h1 = __floats2bfloat162_rn(v.z, v.w);
    __nv_bfloat162 l0 = __floats2bfloat162_rn(v.x - __bfloat162float(h0.x),
                                              v.y - __bfloat162float(h0.y));
    __nv_bfloat162 l1 = __floats2bfloat162_rn(v.z - __bfloat162float(h1.x),
                                              v.w - __bfloat162float(h1.y));
    *ph = make_uint2(*(uint32_t*)&h0, *(uint32_t*)&h1);
    *pl = make_uint2(*(uint32_t*)&l0, *(uint32_t*)&l1);
}

// ===========================================================================
// gemm_qkv: merged q/k/v projections. fp32-input bf16x3 NT GEMM (R13 gemm_w
// core), 128x128 tile, BK=16. blockIdx.z selects operands. Output: bf16 hi/lo
// scatter to head-major [b,h,s,d].
// ===========================================================================
__global__ void __launch_bounds__(256, 2) gemm_qkv(
    const float* __restrict__ Aq, const float* __restrict__ Ak, const float* __restrict__ Av,
    const float* __restrict__ Wq, const float* __restrict__ Wk, const float* __restrict__ Wv,
    const float* __restrict__ bq, const float* __restrict__ bk, const float* __restrict__ bv,
    __nv_bfloat16* __restrict__ qh, __nv_bfloat16* __restrict__ ql,
    __nv_bfloat16* __restrict__ kh, __nv_bfloat16* __restrict__ kl,
    __nv_bfloat16* __restrict__ vh, __nv_bfloat16* __restrict__ vl)
{
    constexpr int BK = 16, SK = 24, K = DM;  // 48B rows: conflict-free ldsm

    __shared__ __nv_bfloat16 Ah[128 * SK], Al[128 * SK];
    __shared__ __nv_bfloat16 Bh[128 * SK], Bl[128 * SK];

    const int z = blockIdx.z;
    const float* A    = (z == 0) ? Aq : (z == 1) ? Ak : Av;
    const float* B    = (z == 0) ? Wq : (z == 1) ? Wk : Wv;
    const float* bias = (z == 0) ? bq : (z == 1) ? bk : bv;
    __nv_bfloat16* Ch = (z == 0) ? qh : (z == 1) ? kh : vh;
    __nv_bfloat16* Cl = (z == 0) ? ql : (z == 1) ? kl : vl;

    const int tid = threadIdx.x, w = tid >> 5, lane = tid & 31;
    const int g = lane >> 2, t = lane & 3;
    const int m0 = blockIdx.y * 128, n0 = blockIdx.x * 128;
    const int wm0 = (w & 3) * 32, wn0 = (w >> 2) * 64;

    const uint32_t ah_b = smem_u32(Ah), al_b = smem_u32(Al);
    const uint32_t bh_b = smem_u32(Bh), bl_b = smem_u32(Bl);

    float acc[2][8][4];
    #pragma unroll
    for (int i = 0; i < 2; i++)
        #pragma unroll
        for (int j = 0; j < 8; j++)
            #pragma unroll
            for (int e = 0; e < 4; e++) acc[i][j][e] = 0.f;

    float4 ra[2], rb[2];
    #pragma unroll
    for (int i = 0; i < 2; i++) {
        int idx = tid + i * 256;
        ra[i] = *(const float4*)(A + (long long)(m0 + (idx >> 2)) * K + (idx & 3) * 4);
        rb[i] = *(const float4*)(B + (long long)(n0 + (idx >> 2)) * K + (idx & 3) * 4);
    }

    for (int k0 = 0; k0 < K; k0 += BK) {
        __syncthreads();
        #pragma unroll
        for (int i = 0; i < 2; i++) {
            int idx = tid + i * 256, r = idx >> 2, c = (idx & 3) * 4;
            cvt_hilo(ra[i], (uint2*)&Ah[r * SK + c], (uint2*)&Al[r * SK + c]);
            cvt_hilo(rb[i], (uint2*)&Bh[r * SK + c], (uint2*)&Bl[r * SK + c]);
        }
        __syncthreads();

        if (k0 + BK < K) {
            #pragma unroll
            for (int i = 0; i < 2; i++) {
                int idx = tid + i * 256;
                ra[i] = *(const float4*)(A + (long long)(m0 + (idx >> 2)) * K + k0 + BK + (idx & 3) * 4);
                rb[i] = *(const float4*)(B + (long long)(n0 + (idx >> 2)) * K + k0 + BK + (idx & 3) * 4);
            }
        }

        const int arow = wm0 + (lane & 7) + ((lane >> 3) & 1) * 8;
        const int acol = (lane >> 4) * 8;
        const int brow = wn0 + (lane & 7) + (lane >> 4) * 8;
        const int bcol = ((lane >> 3) & 1) * 8;

        uint32_t af[2][4], afl[2][4], bf[4][4], bfl[4][4];
        #pragma unroll
        for (int f = 0; f < 2; f++) {
            uint32_t off = ((arow + f * 16) * SK + acol) * 2;
            ldsm4(af[f],  ah_b + off);
            ldsm4(afl[f], al_b + off);
        }
        #pragma unroll
        for (int p = 0; p < 4; p++) {
            uint32_t off = ((brow + p * 16) * SK + bcol) * 2;
            ldsm4(bf[p],  bh_b + off);
            ldsm4(bfl[p], bl_b + off);
        }

        #pragma unroll
        for (int mf = 0; mf < 2; mf++)
            #pragma unroll
            for (int nf = 0; nf < 8; nf++) {
                const uint32_t* bp = &bf[nf >> 1][(nf & 1) * 2];
                const uint32_t* lp = &bfl[nf >> 1][(nf & 1) * 2];
                mma16(acc[mf][nf], afl[mf], bp);
                mma16(acc[mf][nf], af[mf],  lp);
                mma16(acc[mf][nf], af[mf],  bp);
            }
    }

    #pragma unroll
    for (int mf = 0; mf < 2; mf++) {
        #pragma unroll
        for (int nf = 0; nf < 8; nf++) {
            const int gn = n0 + wn0 + nf * 8 + 2 * t;
            float b0 = __ldg(&bias[gn]), b1 = __ldg(&bias[gn + 1]);
            #pragma unroll
            for (int h = 0; h < 2; h++) {
                const int gm = m0 + wm0 + mf * 16 + g + h * 8;
                float v0 = acc[mf][nf][h * 2 + 0] + b0;
                float v1 = acc[mf][nf][h * 2 + 1] + b1;
                int b = gm >> 11, s = gm & (SS - 1);
                int hh = gn >> 6, d = gn & 63;
                long long idx = (((long long)(b * HH + hh)) * SS + s) * DK + d;
                __nv_bfloat162 hp = __floats2bfloat162_rn(v0, v1);
                __nv_bfloat162 lp = __floats2bfloat162_rn(v0 - __bfloat162float(hp.x),
                                                          v1 - __bfloat162float(hp.y));
                *(uint32_t*)&Ch[idx] = *(uint32_t*)&hp;
                *(uint32_t*)&Cl[idx] = *(uint32_t*)&lp;
            }
        }
    }
}

// ===========================================================================
// gemm_fc (R13 gemm_w<0>): fp32-input bf16x3 NT GEMM, 128x128, fp32 C.
// ===========================================================================
__global__ void __launch_bounds__(256, 2) gemm_fc(
    const float* __restrict__ A, const float* __restrict__ B,
    const float* __restrict__ bias, float* __restrict__ C, int N, int K)
{
    constexpr int BK = 16, SK = 24;

    __shared__ __nv_bfloat16 Ah[128 * SK], Al[128 * SK];
    __shared__ __nv_bfloat16 Bh[128 * SK], Bl[128 * SK];

    const int tid = threadIdx.x, w = tid >> 5, lane = tid & 31;
    const int g = lane >> 2, t = lane & 3;
    const int m0 = blockIdx.y * 128, n0 = blockIdx.x * 128;
    const int wm0 = (w & 3) * 32, wn0 = (w >> 2) * 64;

    const uint32_t ah_b = smem_u32(Ah), al_b = smem_u32(Al);
    const uint32_t bh_b = smem_u32(Bh), bl_b = smem_u32(Bl);

    float acc[2][8][4];
    #pragma unroll
    for (int i = 0; i < 2; i++)
        #pragma unroll
        for (int j = 0; j < 8; j++)
            #pragma unroll
            for (int e = 0; e < 4; e++) acc[i][j][e] = 0.f;

    float4 ra[2], rb[2];
    #pragma unroll
    for (int i = 0; i < 2; i++) {
        int idx = tid + i * 256;
        ra[i] = *(const float4*)(A + (long long)(m0 + (idx >> 2)) * K + (idx & 3) * 4);
        rb[i] = *(const float4*)(B + (long long)(n0 + (idx >> 2)) * K + (idx & 3) * 4);
    }

    for (int k0 = 0; k0 < K; k0 += BK) {
        __syncthreads();
        #pragma unroll
        for (int i = 0; i < 2; i++) {
            int idx = tid + i * 256, r = idx >> 2, c = (idx & 3) * 4;
            cvt_hilo(ra[i], (uint2*)&Ah[r * SK + c], (uint2*)&Al[r * SK + c]);
            cvt_hilo(rb[i], (uint2*)&Bh[r * SK + c], (uint2*)&Bl[r * SK + c]);
        }
        __syncthreads();

        if (k0 + BK < K) {
            #pragma unroll
            for (int i = 0; i < 2; i++) {
                int idx = tid + i * 256;
                ra[i] = *(const float4*)(A + (long long)(m0 + (idx >> 2)) * K + k0 + BK + (idx & 3) * 4);
                rb[i] = *(const float4*)(B + (long long)(n0 + (idx >> 2)) * K + k0 + BK + (idx & 3) * 4);
            }
        }

        const int arow = wm0 + (lane & 7) + ((lane >> 3) & 1) * 8;
        const int acol = (lane >> 4) * 8;
        const int brow = wn0 + (lane & 7) + (lane >> 4) * 8;
        const int bcol = ((lane >> 3) & 1) * 8;

        uint32_t af[2][4], afl[2][4], bf[4][4], bfl[4][4];
        #pragma unroll
        for (int f = 0; f < 2; f++) {
            uint32_t off = ((arow + f * 16) * SK + acol) * 2;
            ldsm4(af[f],  ah_b + off);
            ldsm4(afl[f], al_b + off);
        }
        #pragma unroll
        for (int p = 0; p < 4; p++) {
            uint32_t off = ((brow + p * 16) * SK + bcol) * 2;
            ldsm4(bf[p],  bh_b + off);
            ldsm4(bfl[p], bl_b + off);
        }

        #pragma unroll
        for (int mf = 0; mf < 2; mf++)
            #pragma unroll
            for (int nf = 0; nf < 8; nf++) {
                const uint32_t* bp = &bf[nf >> 1][(nf & 1) * 2];
                const uint32_t* lp = &bfl[nf >> 1][(nf & 1) * 2];
                mma16(acc[mf][nf], afl[mf], bp);
                mma16(acc[mf][nf], af[mf],  lp);
                mma16(acc[mf][nf], af[mf],  bp);
            }
    }

    #pragma unroll
    for (int mf = 0; mf < 2; mf++) {
        #pragma unroll
        for (int nf = 0; nf < 8; nf++) {
            const int gn = n0 + wn0 + nf * 8 + 2 * t;
            float b0 = __ldg(&bias[gn]), b1 = __ldg(&bias[gn + 1]);
            #pragma unroll
            for (int h = 0; h < 2; h++) {
                const int gm = m0 + wm0 + mf * 16 + g + h * 8;
                float2 p = {acc[mf][nf][h * 2 + 0] + b0, acc[mf][nf][h * 2 + 1] + b1};
                *(float2*)&C[(long long)gm * N + gn] = p;
            }
        }
    }
}

// ===========================================================================
// gemm_pv: P (fp32, cvt-staged) @ V (bf16 hi/lo [bh][s][d], cp.async + trans
// ldsm). 128x64 tile, BK=32. Out: fp32 ao (b,s,h,d) flat.
// ===========================================================================
__global__ void __launch_bounds__(256, 2) gemm_pv(
    const float* __restrict__ attn,
    const __nv_bfloat16* __restrict__ Vh, const __nv_bfloat16* __restrict__ Vl,
    float* __restrict__ ao)
{
    constexpr int BK = 32, SK = 40;   // P smem stride
    constexpr int SKV = 72;           // V smem stride (144B rows, conflict-free trans)

    __shared__ __nv_bfloat16 Ah[128 * SK], Al[128 * SK];   // P hi/lo
    __shared__ __nv_bfloat16 VH[BK * SKV], VL[BK * SKV];   // V k-major [k][d]

    const int bz = blockIdx.z;
    const float* A = attn + (long long)bz * SS * SS;
    const __nv_bfloat16* VhB = Vh + (long long)bz * SS * DK;
    const __nv_bfloat16* VlB = Vl + (long long)bz * SS * DK;
    const int K = SS;

    const int tid = threadIdx.x, w = tid >> 5, lane = tid & 31;
    const int g = lane >> 2, t = lane & 3;
    const int m0 = blockIdx.y * 128;
    const int wm0 = (w & 3) * 32, wn0 = (w >> 2) * 32;

    const uint32_t ah_b = smem_u32(Ah), al_b = smem_u32(Al);
    const uint32_t vh_b = smem_u32(VH), vl_b = smem_u32(VL);

    float acc[2][4][4];
    #pragma unroll
    for (int i = 0; i < 2; i++)
        #pragma unroll
        for (int j = 0; j < 4; j++)
            #pragma unroll
            for (int e = 0; e < 4; e++) acc[i][j][e] = 0.f;

    float4 ra[4];
    #pragma unroll
    for (int i = 0; i < 4; i++) {
        int idx = tid + i * 256;
        ra[i] = *(const float4*)(A + (long long)(m0 + (idx >> 3)) * K + (idx & 7) * 4);
    }

    for (int k0 = 0; k0 < K; k0 += BK) {
        __syncthreads();
        // stage P hi/lo from prefetched regs
        #pragma unroll
        for (int i = 0; i < 4; i++) {
            int idx = tid + i * 256, r = idx >> 3, c = (idx & 7) * 4;
            cvt_hilo(ra[i], (uint2*)&Ah[r * SK + c], (uint2*)&Al[r * SK + c]);
        }
        // stage V k-rows via cp.async: row r = V[(k0+r)][0..63] hi/lo (128B = 8x16B)
        {
            int r = tid >> 3, c = tid & 7;
            long long src = ((long long)(k0 + r)) * DK + c * 8;
            uint32_t so = (uint32_t)(r * SKV + c * 8) * 2;
            cp16(vh_b + so, VhB + src);
            cp16(vl_b + so, VlB + src);
        }
        asm volatile("cp.async.commit_group;");

        if (k0 + BK < K) {
            #pragma unroll
            for (int i = 0; i < 4; i++) {
                int idx = tid + i * 256;
                ra[i] = *(const float4*)(A + (long long)(m0 + (idx >> 3)) * K + k0 + BK + (idx & 7) * 4);
            }
        }
        asm volatile("cp.async.wait_group 0;");
        __syncthreads();

        #pragma unroll
        for (int ks = 0; ks < 2; ks++) {
            const int arow = wm0 + (lane & 7) + ((lane >> 3) & 1) * 8;
            const int acol = ks * 16 + (lane >> 4) * 8;
            // trans-ldsm addressing: rows = k, cols = d
            const int krow = ks * 16 + (lane & 15);

            uint32_t af[2][4], afl[2][4], bf[2][4], bfl[2][4];
            #pragma unroll
            for (int f = 0; f < 2; f++) {
                uint32_t off = ((arow + f * 16) * SK + acol) * 2;
                ldsm4(af[f],  ah_b + off);
                ldsm4(afl[f], al_b + off);
            }
            #pragma unroll
            for (int p = 0; p < 2; p++) {
                int dcol = wn0 + p * 16 + (lane >> 4) * 8;
                uint32_t off = (krow * SKV + dcol) * 2;
                ldsm4t(bf[p],  vh_b + off);
                ldsm4t(bfl[p], vl_b + off);
            }

            #pragma unroll
            for (int mf = 0; mf < 2; mf++)
                #pragma unroll
                for (int nf = 0; nf < 4; nf++) {
                    const uint32_t* bp = &bf[nf >> 1][(nf & 1) * 2];
                    const uint32_t* lp = &bfl[nf >> 1][(nf & 1) * 2];
                    mma16(acc[mf][nf], afl[mf], bp);
                    mma16(acc[mf][nf], af[mf],  lp);
                    mma16(acc[mf][nf], af[mf],  bp);
                }
        }
    }

    const int b = bz >> 4, head = bz & 15;
    #pragma unroll
    for (int mf = 0; mf < 2; mf++) {
        #pragma unroll
        for (int nf = 0; nf < 4; nf++) {
            const int gn = wn0 + nf * 8 + 2 * t;
            #pragma unroll
            for (int h = 0; h < 2; h++) {
                const int gm = m0 + wm0 + mf * 16 + g + h * 8;
                float2 p = {acc[mf][nf][h * 2], acc[mf][nf][h * 2 + 1]};
                *(float2*)&ao[((long long)(b * SS + gm)) * DM + head * DK + gn] = p;
            }
        }
    }
}

// ===========================================================================
// Logits GEMM (proven R7): bf16 hi/lo inputs via cp.async. C=(q@k^T)/8 per head.
// ===========================================================================
__global__ void __launch_bounds__(256, 2) gemm_lg(
    const __nv_bfloat16* __restrict__ Qh, const __nv_bfloat16* __restrict__ Ql,
    const __nv_bfloat16* __restrict__ Kh, const __nv_bfloat16* __restrict__ Kl,
    float* __restrict__ C)
{
    constexpr int SK = 72;
    __nv_bfloat16* sm = (__nv_bfloat16*)dynsm;
    __nv_bfloat16* tiles[4] = { sm, sm + 128 * SK, sm + 2 * 128 * SK, sm + 3 * 128 * SK };

    const int bh = blockIdx.z;
    const int tid = threadIdx.x, w = tid >> 5, lane = tid & 31;
    const int g = lane >> 2, t = lane & 3;
    const int m0 = blockIdx.y * 128, n0 = blockIdx.x * 128;
    const int wm0 = (w & 3) * 32, wn0 = (w >> 2) * 64;

    const __nv_bfloat16* srcs[4] = {
        Qh + (long long)bh * SS * DK + (long long)m0 * DK,
        Ql + (long long)bh * SS * DK + (long long)m0 * DK,
        Kh + (long long)bh * SS * DK + (long long)n0 * DK,
        Kl + (long long)bh * SS * DK + (long long)n0 * DK };

    #pragma unroll
    for (int a = 0; a < 4; a++) {
        uint32_t dst = smem_u32(tiles[a]);
        #pragma unroll
        for (int i = 0; i < 4; i++) {
            int idx = tid + i * 256;
            int r = idx >> 3, c = idx & 7;
            cp16(dst + (r * SK + c * 8) * 2, srcs[a] + r * 64 + c * 8);
        }
    }
    asm volatile("cp.async.commit_group;");
    asm volatile("cp.async.wait_group 0;");
    __syncthreads();

    const uint32_t ah_b = smem_u32(tiles[0]), al_b = smem_u32(tiles[1]);
    const uint32_t bh_b = smem_u32(tiles[2]), bl_b = smem_u32(tiles[3]);

    float acc[2][8][4];
    #pragma unroll
    for (int i = 0; i < 2; i++)
        #pragma unroll
        for (int j = 0; j < 8; j++)
            #pragma unroll
            for (int e = 0; e < 4; e++) acc[i][j][e] = 0.f;

    #pragma unroll
    for (int ks = 0; ks < 4; ks++) {
        const int arow = wm0 + (lane & 7) + ((lane >> 3) & 1) * 8;
        const int acol = ks * 16 + (lane >> 4) * 8;
        const int brow = wn0 + (lane & 7) + (lane >> 4) * 8;
        const int bcol = ((lane >> 3) & 1) * 8 + ks * 16;

        uint32_t af[2][4], afl[2][4], bf[4][4], bfl[4][4];
        #pragma unroll
        for (int f = 0; f < 2; f++) {
            uint32_t off = ((arow + f * 16) * SK + acol) * 2;
            ldsm4(af[f],  ah_b + off);
            ldsm4(afl[f], al_b + off);
        }
        #pragma unroll
        for (int p = 0; p < 4; p++) {
            uint32_t off = ((brow + p * 16) * SK + bcol) * 2;
            ldsm4(bf[p],  bh_b + off);
            ldsm4(bfl[p], bl_b + off);
        }

        #pragma unroll
        for (int mf = 0; mf < 2; mf++)
            #pragma unroll
            for (int nf = 0; nf < 8; nf++) {
                const uint32_t* bp = &bf[nf >> 1][(nf & 1) * 2];
                const uint32_t* lp = &bfl[nf >> 1][(nf & 1) * 2];
                mma16(acc[mf][nf], afl[mf], bp);
                mma16(acc[mf][nf], af[mf],  lp);
                mma16(acc[mf][nf], af[mf],  bp);
            }
    }

    float* Cb = C + (long long)bh * SS * SS;
    #pragma unroll
    for (int mf = 0; mf < 2; mf++)
        #pragma unroll
        for (int nf = 0; nf < 8; nf++) {
            const int gn = n0 + wn0 + nf * 8 + 2 * t;
            #pragma unroll
            for (int h = 0; h < 2; h++) {
                const int gm = m0 + wm0 + mf * 16 + g + h * 8;
                float2 p = {acc[mf][nf][h * 2] * 0.125f, acc[mf][nf][h * 2 + 1] * 0.125f};
                *(float2*)&Cb[(long long)gm * SS + gn] = p;
            }
        }
}

// ===========================================================================
// Sparsemax (proven R7): one WARP per row of 2048, in-place, shfl-only.
// ===========================================================================
__global__ void __launch_bounds__(256) sparsemax_kernel(float* __restrict__ attn)
{
    const int row = blockIdx.x * 8 + (threadIdx.x >> 5);
    const int lane = threadIdx.x & 31;
    float* z = attn + (long long)row * SS;

    float4 v[16];
    #pragma unroll
    for (int i = 0; i < 16; i++) v[i] = *(const float4*)(z + i * 128 + lane * 4);

    float mx = -1e30f;
    #pragma unroll
    for (int i = 0; i < 16; i++)
        mx = fmaxf(mx, fmaxf(fmaxf(v[i].x, v[i].y), fmaxf(v[i].z, v[i].w)));
    #pragma unroll
    for (int o = 16; o; o >>= 1) mx = fmaxf(mx, __shfl_xor_sync(0xffffffffu, mx, o));

    float lo = mx - 1.f, hi = mx;
    for (int it = 0; it < 12; it++) {
        float mid = 0.5f * (lo + hi);
        float s = 0.f;
        #pragma unroll
        for (int i = 0; i < 16; i++) {
            s += fmaxf(v[i].x - mid, 0.f) + fmaxf(v[i].y - mid, 0.f);
            s += fmaxf(v[i].z - mid, 0.f) + fmaxf(v[i].w - mid, 0.f);
        }
        #pragma unroll
        for (int o = 16; o; o >>= 1) s += __shfl_xor_sync(0xffffffffu, s, o);
        if (s >= 1.f) lo = mid; else hi = mid;
    }

    float tau = lo;
    for (int it = 0; it < 8; it++) {
        float s = 0.f, c = 0.f;
        #pragma unroll
        for (int i = 0; i < 16; i++) {
            if (v[i].x > tau) { s += v[i].x; c += 1.f; }
            if (v[i].y > tau) { s += v[i].y; c += 1.f; }
            if (v[i].z > tau) { s += v[i].z; c += 1.f; }
            if (v[i].w > tau) { s += v[i].w; c += 1.f; }
        }
        #pragma unroll
        for (int o = 16; o; o >>= 1) {
            s += __shfl_xor_sync(0xffffffffu, s, o);
            c += __shfl_xor_sync(0xffffffffu, c, o);
        }
        float nt = (s - 1.f) / c;   // c >= 1 (row max in support)
        if (nt == tau) break;
        tau = nt;
    }

    #pragma unroll
    for (int i = 0; i < 16; i++) {
        float4 o;
        o.x = fmaxf(v[i].x - tau, 0.f);
        o.y = fmaxf(v[i].y - tau, 0.f);
        o.z = fmaxf(v[i].z - tau, 0.f);
        o.w = fmaxf(v[i].w - tau, 0.f);
        *(float4*)(z + i * 128 + lane * 4) = o;
    }
}

// ---------------------------------------------------------------------------
extern "C" void kernel_launch(void* const* d_in, const int* in_sizes, int n_in,
                              void* d_out, int out_size)
{
    const float* query = (const float*)d_in[0];
    const float* key   = (const float*)d_in[1];
    const float* value = (const float*)d_in[2];
    const float* Wq  = (const float*)d_in[3];  const float* bq  = (const float*)d_in[4];
    const float* Wk  = (const float*)d_in[5];  const float* bk  = (const float*)d_in[6];
    const float* Wv  = (const float*)d_in[7];  const float* bv  = (const float*)d_in[8];
    const float* Wfc = (const float*)d_in[9];  const float* bfc = (const float*)d_in[10];

    float* out  = (float*)d_out;
    float* attn = out + OUT_ELEMS;

    __nv_bfloat16 *pqh, *pql, *pkh, *pkl, *pvh, *pvl;
    float *pao;
    cudaGetSymbolAddress((void**)&pqh, g_qh);  cudaGetSymbolAddress((void**)&pql, g_ql);
    cudaGetSymbolAddress((void**)&pkh, g_kh);  cudaGetSymbolAddress((void**)&pkl, g_kl);
    cudaGetSymbolAddress((void**)&pvh, g_vh);  cudaGetSymbolAddress((void**)&pvl, g_vl);
    cudaGetSymbolAddress((void**)&pao, g_ao);

    const int LG_SMEM = 4 * 128 * 72 * 2;  // 73728 B
    cudaFuncSetAttribute(gemm_lg, cudaFuncAttributeMaxDynamicSharedMemorySize, LG_SMEM);

    dim3 blk(256);

    // 1) Merged projections: q,k,v -> bf16 hi/lo head-major [bh][s][d]
    gemm_qkv<<<dim3(DM/128, MM/128, 3), blk>>>(
        query, key, value, Wq, Wk, Wv, bq, bk, bv,
        pqh, pql, pkh, pkl, pvh, pvl);

    // 2) logits = q @ k^T / 8 -> attention slice of d_out
    gemm_lg<<<dim3(SS/128, SS/128, BB*HH), blk, LG_SMEM>>>(pqh, pql, pkh, pkl, attn);

    // 3) sparsemax in place (warp per row)
    sparsemax_kernel<<<BB*HH*SS/8, 256>>>(attn);

    // 4) attn_out = P @ V -> fp32 (b,s,h,d) flat
    gemm_pv<<<dim3(1, SS/128, BB*HH), blk>>>(attn, pvh, pvl, pao);

    // 5) output = attn_out @ Wfc^T + bfc
    gemm_fc<<<dim3(DM/128, MM/128, 1), blk>>>(pao, Wfc, bfc, out, DM, DM);
}

// round 17
// speedup vs baseline: 1.0522x; 1.0261x over previous
#include <cuda_runtime.h>
#include <cuda_bf16.h>
#include <cstdint>

#define BB   2
#define SS   2048
#define HH   16
#define DK   64
#define DM   1024
#define MM   (BB*SS)
#define OUT_ELEMS  (4194304)

// Scratch (allocation-free rule: device globals)
__device__ __nv_bfloat16 g_qh[BB*HH*SS*DK], g_ql[BB*HH*SS*DK];  // q proj hi/lo [bh][s][d]
__device__ __nv_bfloat16 g_kh[BB*HH*SS*DK], g_kl[BB*HH*SS*DK];  // k proj hi/lo
__device__ float g_v [BB*HH*DK*SS];                              // v fp32 [bh][d][s]
__device__ float g_ao[MM*DM];                                    // attn_out fp32 (b,s,h,d)

// single dynamic-smem symbol (used by gemm_lg)
extern __shared__ char dynsm[];

// ---------------------------------------------------------------------------
__device__ __forceinline__ void mma16(float* c, const uint32_t* a, const uint32_t* b) {
    asm volatile("mma.sync.aligned.m16n8k16.row.col.f32.bf16.bf16.f32 "
        "{%0,%1,%2,%3},{%4,%5,%6,%7},{%8,%9},{%0,%1,%2,%3};"
        : "+f"(c[0]), "+f"(c[1]), "+f"(c[2]), "+f"(c[3])
        : "r"(a[0]), "r"(a[1]), "r"(a[2]), "r"(a[3]), "r"(b[0]), "r"(b[1]));
}

__device__ __forceinline__ void ldsm4(uint32_t* r, uint32_t addr) {
    asm volatile("ldmatrix.sync.aligned.m8n8.x4.shared.b16 {%0,%1,%2,%3}, [%4];"
        : "=r"(r[0]), "=r"(r[1]), "=r"(r[2]), "=r"(r[3]) : "r"(addr));
}

__device__ __forceinline__ uint32_t smem_u32(const void* p) {
    return (uint32_t)__cvta_generic_to_shared(p);
}

__device__ __forceinline__ void cp16(uint32_t dst, const void* src) {
    asm volatile("cp.async.cg.shared.global [%0], [%1], 16;" :: "r"(dst), "l"(src));
}

// convert 4 floats -> 4 hi bf16 (8B) + 4 lo bf16 (8B)
__device__ __forceinline__ void cvt_hilo(const float4 v, uint2* ph, uint2* pl) {
    __nv_bfloat162 h0 = __floats2bfloat162_rn(v.x, v.y);
    __nv_bfloat162 h1 = __floats2bfloat162_rn(v.z, v.w);
    __nv_bfloat162 l0 = __floats2bfloat162_rn(v.x - __bfloat162float(h0.x),
                                              v.y - __bfloat162float(h0.y));
    __nv_bfloat162 l1 = __floats2bfloat162_rn(v.z - __bfloat162float(h1.x),
                                              v.w - __bfloat162float(h1.y));
    *ph = make_uint2(*(uint32_t*)&h0, *(uint32_t*)&h1);
    *pl = make_uint2(*(uint32_t*)&l0, *(uint32_t*)&l1);
}

// ===========================================================================
// gemm_w (proven R13): fp32-input bf16x3 NT GEMM, 128x128 tile, BK=16.
// MODE: 0 fp32 row-major C; 1 bf16 hi/lo scatter [b,h,s,d]; 2 fp32 scatter [b,h,d,s]
// ===========================================================================
template<int MODE>
__global__ void __launch_bounds__(256, 2) gemm_w(
    const float* __restrict__ A, const float* __restrict__ B,
    const float* __restrict__ bias, float* __restrict__ C,
    __nv_bfloat16* __restrict__ Ch, __nv_bfloat16* __restrict__ Cl,
    int N, int K, float scale)
{
    constexpr int BK = 16, SK = 24;  // 48B rows: conflict-free ldsm

    __shared__ __nv_bfloat16 Ah[128 * SK], Al[128 * SK];
    __shared__ __nv_bfloat16 Bh[128 * SK], Bl[128 * SK];

    const int tid = threadIdx.x, w = tid >> 5, lane = tid & 31;
    const int g = lane >> 2, t = lane & 3;
    const int m0 = blockIdx.y * 128, n0 = blockIdx.x * 128;
    const int wm0 = (w & 3) * 32, wn0 = (w >> 2) * 64;

    const uint32_t ah_b = smem_u32(Ah), al_b = smem_u32(Al);
    const uint32_t bh_b = smem_u32(Bh), bl_b = smem_u32(Bl);

    float acc[2][8][4];
    #pragma unroll
    for (int i = 0; i < 2; i++)
        #pragma unroll
        for (int j = 0; j < 8; j++)
            #pragma unroll
            for (int e = 0; e < 4; e++) acc[i][j][e] = 0.f;

    float4 ra[2], rb[2];
    #pragma unroll
    for (int i = 0; i < 2; i++) {
        int idx = tid + i * 256;
        ra[i] = *(const float4*)(A + (long long)(m0 + (idx >> 2)) * K + (idx & 3) * 4);
        rb[i] = *(const float4*)(B + (long long)(n0 + (idx >> 2)) * K + (idx & 3) * 4);
    }

    for (int k0 = 0; k0 < K; k0 += BK) {
        __syncthreads();
        #pragma unroll
        for (int i = 0; i < 2; i++) {
            int idx = tid + i * 256, r = idx >> 2, c = (idx & 3) * 4;
            cvt_hilo(ra[i], (uint2*)&Ah[r * SK + c], (uint2*)&Al[r * SK + c]);
            cvt_hilo(rb[i], (uint2*)&Bh[r * SK + c], (uint2*)&Bl[r * SK + c]);
        }
        __syncthreads();

        if (k0 + BK < K) {
            #pragma unroll
            for (int i = 0; i < 2; i++) {
                int idx = tid + i * 256;
                ra[i] = *(const float4*)(A + (long long)(m0 + (idx >> 2)) * K + k0 + BK + (idx & 3) * 4);
                rb[i] = *(const float4*)(B + (long long)(n0 + (idx >> 2)) * K + k0 + BK + (idx & 3) * 4);
            }
        }

        const int arow = wm0 + (lane & 7) + ((lane >> 3) & 1) * 8;
        const int acol = (lane >> 4) * 8;
        const int brow = wn0 + (lane & 7) + (lane >> 4) * 8;
        const int bcol = ((lane >> 3) & 1) * 8;

        uint32_t af[2][4], afl[2][4], bf[4][4], bfl[4][4];
        #pragma unroll
        for (int f = 0; f < 2; f++) {
            uint32_t off = ((arow + f * 16) * SK + acol) * 2;
            ldsm4(af[f],  ah_b + off);
            ldsm4(afl[f], al_b + off);
        }
        #pragma unroll
        for (int p = 0; p < 4; p++) {
            uint32_t off = ((brow + p * 16) * SK + bcol) * 2;
            ldsm4(bf[p],  bh_b + off);
            ldsm4(bfl[p], bl_b + off);
        }

        #pragma unroll
        for (int mf = 0; mf < 2; mf++)
            #pragma unroll
            for (int nf = 0; nf < 8; nf++) {
                const uint32_t* bp = &bf[nf >> 1][(nf & 1) * 2];
                const uint32_t* lp = &bfl[nf >> 1][(nf & 1) * 2];
                mma16(acc[mf][nf], afl[mf], bp);
                mma16(acc[mf][nf], af[mf],  lp);
                mma16(acc[mf][nf], af[mf],  bp);
            }
    }

    #pragma unroll
    for (int mf = 0; mf < 2; mf++) {
        #pragma unroll
        for (int nf = 0; nf < 8; nf++) {
            const int gn = n0 + wn0 + nf * 8 + 2 * t;
            float b0 = 0.f, b1 = 0.f;
            if (bias) { b0 = __ldg(&bias[gn]); b1 = __ldg(&bias[gn + 1]); }
            #pragma unroll
            for (int h = 0; h < 2; h++) {
                const int gm = m0 + wm0 + mf * 16 + g + h * 8;
                float v0 = acc[mf][nf][h * 2 + 0] * scale + b0;
                float v1 = acc[mf][nf][h * 2 + 1] * scale + b1;
                if (MODE == 0) {
                    float2 p = {v0, v1};
                    *(float2*)&C[(long long)gm * N + gn] = p;
                } else if (MODE == 1) {
                    int b = gm >> 11, s = gm & (SS - 1);
                    int hh = gn >> 6, d = gn & 63;
                    long long idx = (((long long)(b * HH + hh)) * SS + s) * DK + d;
                    __nv_bfloat162 hp = __floats2bfloat162_rn(v0, v1);
                    __nv_bfloat162 lp = __floats2bfloat162_rn(v0 - __bfloat162float(hp.x),
                                                              v1 - __bfloat162float(hp.y));
                    *(uint32_t*)&Ch[idx] = *(uint32_t*)&hp;
                    *(uint32_t*)&Cl[idx] = *(uint32_t*)&lp;
                } else { // MODE 2
                    int b = gm >> 11, s = gm & (SS - 1);
                    int hh = gn >> 6, d = gn & 63;
                    C[(((long long)(b * HH + hh)) * DK + d) * SS + s] = v0;
                    C[(((long long)(b * HH + hh)) * DK + d + 1) * SS + s] = v1;
                }
            }
        }
    }
}

// ===========================================================================
// gemm_pv: P @ V^T per head, 256x64 tile (ONE WAVE: 256 CTAs), BK=16.
// 8 warps all along M, warp tile 32x64. A=P fp32, B=V fp32 [d][s].
// Out: fp32 ao (b,s,h,d) flat.
// ===========================================================================
__global__ void __launch_bounds__(256, 2) gemm_pv(
    const float* __restrict__ attn, const float* __restrict__ V,
    float* __restrict__ ao)
{
    constexpr int BK = 16, SK = 24;

    __shared__ __nv_bfloat16 Ah[256 * SK], Al[256 * SK];   // 24 KB
    __shared__ __nv_bfloat16 Bh[64 * SK],  Bl[64 * SK];    //  6 KB

    const int bz = blockIdx.z;
    const float* A = attn + (long long)bz * SS * SS;
    const float* B = V + (long long)bz * DK * SS;
    const int K = SS;

    const int tid = threadIdx.x, w = tid >> 5, lane = tid & 31;
    const int g = lane >> 2, t = lane & 3;
    const int m0 = blockIdx.y * 256;
    const int wm0 = w * 32;

    const uint32_t ah_b = smem_u32(Ah), al_b = smem_u32(Al);
    const uint32_t bh_b = smem_u32(Bh), bl_b = smem_u32(Bl);

    float acc[2][8][4];
    #pragma unroll
    for (int i = 0; i < 2; i++)
        #pragma unroll
        for (int j = 0; j < 8; j++)
            #pragma unroll
            for (int e = 0; e < 4; e++) acc[i][j][e] = 0.f;

    // A: 256x16 fp32 = 1024 float4, 4/thread. B: 64x16 = 256 float4, 1/thread.
    float4 ra[4], rb;
    #pragma unroll
    for (int i = 0; i < 4; i++) {
        int idx = tid + i * 256;
        ra[i] = *(const float4*)(A + (long long)(m0 + (idx >> 2)) * K + (idx & 3) * 4);
    }
    rb = *(const float4*)(B + (long long)(tid >> 2) * K + (tid & 3) * 4);

    for (int k0 = 0; k0 < K; k0 += BK) {
        __syncthreads();
        #pragma unroll
        for (int i = 0; i < 4; i++) {
            int idx = tid + i * 256, r = idx >> 2, c = (idx & 3) * 4;
            cvt_hilo(ra[i], (uint2*)&Ah[r * SK + c], (uint2*)&Al[r * SK + c]);
        }
        {
            int r = tid >> 2, c = (tid & 3) * 4;
            cvt_hilo(rb, (uint2*)&Bh[r * SK + c], (uint2*)&Bl[r * SK + c]);
        }
        __syncthreads();

        if (k0 + BK < K) {
            #pragma unroll
            for (int i = 0; i < 4; i++) {
                int idx = tid + i * 256;
                ra[i] = *(const float4*)(A + (long long)(m0 + (idx >> 2)) * K + k0 + BK + (idx & 3) * 4);
            }
            rb = *(const float4*)(B + (long long)(tid >> 2) * K + k0 + BK + (tid & 3) * 4);
        }

        const int arow = wm0 + (lane & 7) + ((lane >> 3) & 1) * 8;
        const int acol = (lane >> 4) * 8;
        const int brow = (lane & 7) + (lane >> 4) * 8;
        const int bcol = ((lane >> 3) & 1) * 8;

        uint32_t af[2][4], afl[2][4], bf[4][4], bfl[4][4];
        #pragma unroll
        for (int f = 0; f < 2; f++) {
            uint32_t off = ((arow + f * 16) * SK + acol) * 2;
            ldsm4(af[f],  ah_b + off);
            ldsm4(afl[f], al_b + off);
        }
        #pragma unroll
        for (int p = 0; p < 4; p++) {
            uint32_t off = ((brow + p * 16) * SK + bcol) * 2;
            ldsm4(bf[p],  bh_b + off);
            ldsm4(bfl[p], bl_b + off);
        }

        #pragma unroll
        for (int mf = 0; mf < 2; mf++)
            #pragma unroll
            for (int nf = 0; nf < 8; nf++) {
                const uint32_t* bp = &bf[nf >> 1][(nf & 1) * 2];
                const uint32_t* lp = &bfl[nf >> 1][(nf & 1) * 2];
                mma16(acc[mf][nf], afl[mf], bp);
                mma16(acc[mf][nf], af[mf],  lp);
                mma16(acc[mf][nf], af[mf],  bp);
            }
    }

    const int b = bz >> 4, head = bz & 15;
    #pragma unroll
    for (int mf = 0; mf < 2; mf++) {
        #pragma unroll
        for (int nf = 0; nf < 8; nf++) {
            const int gn = nf * 8 + 2 * t;
            #pragma unroll
            for (int h = 0; h < 2; h++) {
                const int gm = m0 + wm0 + mf * 16 + g + h * 8;
                float2 p = {acc[mf][nf][h * 2], acc[mf][nf][h * 2 + 1]};
                *(float2*)&ao[((long long)(b * SS + gm)) * DM + head * DK + gn] = p;
            }
        }
    }
}

// ===========================================================================
// Logits GEMM (proven R7): bf16 hi/lo inputs via cp.async. C=(q@k^T)/8 per head.
// ===========================================================================
__global__ void __launch_bounds__(256, 2) gemm_lg(
    const __nv_bfloat16* __restrict__ Qh, const __nv_bfloat16* __restrict__ Ql,
    const __nv_bfloat16* __restrict__ Kh, const __nv_bfloat16* __restrict__ Kl,
    float* __restrict__ C)
{
    constexpr int SK = 72;
    __nv_bfloat16* sm = (__nv_bfloat16*)dynsm;
    __nv_bfloat16* tiles[4] = { sm, sm + 128 * SK, sm + 2 * 128 * SK, sm + 3 * 128 * SK };

    const int bh = blockIdx.z;
    const int tid = threadIdx.x, w = tid >> 5, lane = tid & 31;
    const int g = lane >> 2, t = lane & 3;
    const int m0 = blockIdx.y * 128, n0 = blockIdx.x * 128;
    const int wm0 = (w & 3) * 32, wn0 = (w >> 2) * 64;

    const __nv_bfloat16* srcs[4] = {
        Qh + (long long)bh * SS * DK + (long long)m0 * DK,
        Ql + (long long)bh * SS * DK + (long long)m0 * DK,
        Kh + (long long)bh * SS * DK + (long long)n0 * DK,
        Kl + (long long)bh * SS * DK + (long long)n0 * DK };

    #pragma unroll
    for (int a = 0; a < 4; a++) {
        uint32_t dst = smem_u32(tiles[a]);
        #pragma unroll
        for (int i = 0; i < 4; i++) {
            int idx = tid + i * 256;
            int r = idx >> 3, c = idx & 7;
            cp16(dst + (r * SK + c * 8) * 2, srcs[a] + r * 64 + c * 8);
        }
    }
    asm volatile("cp.async.commit_group;");
    asm volatile("cp.async.wait_group 0;");
    __syncthreads();

    const uint32_t ah_b = smem_u32(tiles[0]), al_b = smem_u32(tiles[1]);
    const uint32_t bh_b = smem_u32(tiles[2]), bl_b = smem_u32(tiles[3]);

    float acc[2][8][4];
    #pragma unroll
    for (int i = 0; i < 2; i++)
        #pragma unroll
        for (int j = 0; j < 8; j++)
            #pragma unroll
            for (int e = 0; e < 4; e++) acc[i][j][e] = 0.f;

    #pragma unroll
    for (int ks = 0; ks < 4; ks++) {
        const int arow = wm0 + (lane & 7) + ((lane >> 3) & 1) * 8;
        const int acol = ks * 16 + (lane >> 4) * 8;
        const int brow = wn0 + (lane & 7) + (lane >> 4) * 8;
        const int bcol = ((lane >> 3) & 1) * 8 + ks * 16;

        uint32_t af[2][4], afl[2][4], bf[4][4], bfl[4][4];
        #pragma unroll
        for (int f = 0; f < 2; f++) {
            uint32_t off = ((arow + f * 16) * SK + acol) * 2;
            ldsm4(af[f],  ah_b + off);
            ldsm4(afl[f], al_b + off);
        }
        #pragma unroll
        for (int p = 0; p < 4; p++) {
            uint32_t off = ((brow + p * 16) * SK + bcol) * 2;
            ldsm4(bf[p],  bh_b + off);
            ldsm4(bfl[p], bl_b + off);
        }

        #pragma unroll
        for (int mf = 0; mf < 2; mf++)
            #pragma unroll
            for (int nf = 0; nf < 8; nf++) {
                const uint32_t* bp = &bf[nf >> 1][(nf & 1) * 2];
                const uint32_t* lp = &bfl[nf >> 1][(nf & 1) * 2];
                mma16(acc[mf][nf], afl[mf], bp);
                mma16(acc[mf][nf], af[mf],  lp);
                mma16(acc[mf][nf], af[mf],  bp);
            }
    }

    float* Cb = C + (long long)bh * SS * SS;
    #pragma unroll
    for (int mf = 0; mf < 2; mf++)
        #pragma unroll
        for (int nf = 0; nf < 8; nf++) {
            const int gn = n0 + wn0 + nf * 8 + 2 * t;
            #pragma unroll
            for (int h = 0; h < 2; h++) {
                const int gm = m0 + wm0 + mf * 16 + g + h * 8;
                float2 p = {acc[mf][nf][h * 2] * 0.125f, acc[mf][nf][h * 2 + 1] * 0.125f};
                *(float2*)&Cb[(long long)gm * SS + gn] = p;
            }
        }
}

// ===========================================================================
// Sparsemax (proven R7): one WARP per row of 2048, in-place, shfl-only.
// ===========================================================================
__global__ void __launch_bounds__(256) sparsemax_kernel(float* __restrict__ attn)
{
    const int row = blockIdx.x * 8 + (threadIdx.x >> 5);
    const int lane = threadIdx.x & 31;
    float* z = attn + (long long)row * SS;

    float4 v[16];
    #pragma unroll
    for (int i = 0; i < 16; i++) v[i] = *(const float4*)(z + i * 128 + lane * 4);

    float mx = -1e30f;
    #pragma unroll
    for (int i = 0; i < 16; i++)
        mx = fmaxf(mx, fmaxf(fmaxf(v[i].x, v[i].y), fmaxf(v[i].z, v[i].w)));
    #pragma unroll
    for (int o = 16; o; o >>= 1) mx = fmaxf(mx, __shfl_xor_sync(0xffffffffu, mx, o));

    float lo = mx - 1.f, hi = mx;
    for (int it = 0; it < 12; it++) {
        float mid = 0.5f * (lo + hi);
        float s = 0.f;
        #pragma unroll
        for (int i = 0; i < 16; i++) {
            s += fmaxf(v[i].x - mid, 0.f) + fmaxf(v[i].y - mid, 0.f);
            s += fmaxf(v[i].z - mid, 0.f) + fmaxf(v[i].w - mid, 0.f);
        }
        #pragma unroll
        for (int o = 16; o; o >>= 1) s += __shfl_xor_sync(0xffffffffu, s, o);
        if (s >= 1.f) lo = mid; else hi = mid;
    }

    float tau = lo;
    for (int it = 0; it < 8; it++) {
        float s = 0.f, c = 0.f;
        #pragma unroll
        for (int i = 0; i < 16; i++) {
            if (v[i].x > tau) { s += v[i].x; c += 1.f; }
            if (v[i].y > tau) { s += v[i].y; c += 1.f; }
            if (v[i].z > tau) { s += v[i].z; c += 1.f; }
            if (v[i].w > tau) { s += v[i].w; c += 1.f; }
        }
        #pragma unroll
        for (int o = 16; o; o >>= 1) {
            s += __shfl_xor_sync(0xffffffffu, s, o);
            c += __shfl_xor_sync(0xffffffffu, c, o);
        }
        float nt = (s - 1.f) / c;   // c >= 1 (row max in support)
        if (nt == tau) break;
        tau = nt;
    }

    #pragma unroll
    for (int i = 0; i < 16; i++) {
        float4 o;
        o.x = fmaxf(v[i].x - tau, 0.f);
        o.y = fmaxf(v[i].y - tau, 0.f);
        o.z = fmaxf(v[i].z - tau, 0.f);
        o.w = fmaxf(v[i].w - tau, 0.f);
        *(float4*)(z + i * 128 + lane * 4) = o;
    }
}

// ---------------------------------------------------------------------------
extern "C" void kernel_launch(void* const* d_in, const int* in_sizes, int n_in,
                              void* d_out, int out_size)
{
    const float* query = (const float*)d_in[0];
    const float* key   = (const float*)d_in[1];
    const float* value = (const float*)d_in[2];
    const float* Wq  = (const float*)d_in[3];  const float* bq  = (const float*)d_in[4];
    const float* Wk  = (const float*)d_in[5];  const float* bk  = (const float*)d_in[6];
    const float* Wv  = (const float*)d_in[7];  const float* bv  = (const float*)d_in[8];
    const float* Wfc = (const float*)d_in[9];  const float* bfc = (const float*)d_in[10];

    float* out  = (float*)d_out;
    float* attn = out + OUT_ELEMS;

    __nv_bfloat16 *pqh, *pql, *pkh, *pkl;
    float *pv, *pao;
    cudaGetSymbolAddress((void**)&pqh, g_qh);  cudaGetSymbolAddress((void**)&pql, g_ql);
    cudaGetSymbolAddress((void**)&pkh, g_kh);  cudaGetSymbolAddress((void**)&pkl, g_kl);
    cudaGetSymbolAddress((void**)&pv,  g_v);
    cudaGetSymbolAddress((void**)&pao, g_ao);

    const int LG_SMEM = 4 * 128 * 72 * 2;  // 73728 B
    cudaFuncSetAttribute(gemm_lg, cudaFuncAttributeMaxDynamicSharedMemorySize, LG_SMEM);

    dim3 blk(256);

    // 1) Projections: q,k -> bf16 hi/lo [bh][s][d]; v -> fp32 [bh][d][s]
    gemm_w<1><<<dim3(DM/128, MM/128, 1), blk>>>(query, Wq, bq, nullptr, pqh, pql, DM, DM, 1.f);
    gemm_w<1><<<dim3(DM/128, MM/128, 1), blk>>>(key,   Wk, bk, nullptr, pkh, pkl, DM, DM, 1.f);
    gemm_w<2><<<dim3(DM/128, MM/128, 1), blk>>>(value, Wv, bv, pv, nullptr, nullptr, DM, DM, 1.f);

    // 2) logits = q @ k^T / 8 -> attention slice of d_out
    gemm_lg<<<dim3(SS/128, SS/128, BB*HH), blk, LG_SMEM>>>(pqh, pql, pkh, pkl, attn);

    // 3) sparsemax in place (warp per row)
    sparsemax_kernel<<<BB*HH*SS/8, 256>>>(attn);

    // 4) attn_out = P @ V^T (V [bh][d][s]) -> fp32 (b,s,h,d); 256-row tiles, one wave
    gemm_pv<<<dim3(1, SS/256, BB*HH), blk>>>(attn, pv, pao);

    // 5) output = attn_out @ Wfc^T + bfc
    gemm_w<0><<<dim3(DM/128, MM/128, 1), blk>>>(pao, Wfc, bfc, out, nullptr, nullptr, DM, DM, 1.f);
}